// round 6
// baseline (speedup 1.0000x reference)
#include <cuda_runtime.h>
#include <math.h>

#define BB 16
#define QQ 2304
#define CC 1204
#define NPB (QQ*CC)        /* 2774016 elements per batch */
#define NF4 (NPB/4)        /* 693504 float4 per batch */
#define KTOP 100
#define CAP 8192           /* global candidate store per batch */
#define SHCAP 5632         /* candidates handled by fast path (shared) */
#define SSTRIDE 169
#define NSAMP 16384        /* 16384*169 = 2768896 <= NPB */
#define TGT 16             /* target sample rank -> E[candidates] ~ 2709 */

__device__ float        g_tauV[BB];
__device__ float        g_tauL[BB];
__device__ unsigned     g_cnt[BB];
__device__ unsigned     g_cand[BB][CAP];
__device__ unsigned     g_samp[BB][NSAMP];   /* compact sampled prob keys */

__device__ __forceinline__ float fsig_fast(float x){ return 1.0f/(1.0f+__expf(-x)); }
__device__ __forceinline__ float fsig_acc (float x){ return 1.0f/(1.0f+  expf(-x)); }

// ---------------------------------------------------------------------------
// Kernel 0a: massively parallel sample gather. One scattered load per thread
// (262144 threads total -> latency fully hidden), writes compact key buffer.
// ---------------------------------------------------------------------------
__global__ __launch_bounds__(256) void k_gather(const float* __restrict__ logits,
                                                const float* __restrict__ obj)
{
    int b = blockIdx.y;
    unsigned s = blockIdx.x*blockDim.x + threadIdx.x;   // 0..16383
    unsigned idx = s*(unsigned)SSTRIDE;
    float lg = __ldg(&logits[(size_t)b*NPB + idx]);
    float v  = fsig_fast(lg);
    unsigned q = idx/(unsigned)CC;
    unsigned c = idx - q*(unsigned)CC;
    if (c == (unsigned)(CC-1)) v *= __ldg(&obj[(size_t)b*QQ + q]);
    g_samp[b][s] = __float_as_uint(v);
    if (blockIdx.x==0 && threadIdx.x==0) g_cnt[b] = 0u;
}

// ---------------------------------------------------------------------------
// Kernel 0b: 3-pass 256-bin histogram refinement over the compact (L2-hot)
// sample buffer. Produces tauV (value space) and tauL (logit space).
// ---------------------------------------------------------------------------
__global__ __launch_bounds__(256) void k_refine(void)
{
    int b = blockIdx.x;
    __shared__ unsigned hist[256];
    __shared__ unsigned sSel, sAbove;
    unsigned tid = threadIdx.x;
    if (tid==0){ sSel=0u; sAbove=0u; }
    __syncthreads();

    const int shifts[3] = {22,14,6};
    for (int pass=0; pass<3; pass++){
        hist[tid]=0u;
        __syncthreads();
        int shift = shifts[pass];
        unsigned prefix = sSel;
        for (unsigned s=tid; s<(unsigned)NSAMP; s+=256u){
            unsigned key = g_samp[b][s];
            bool ok = (pass==0) || ((key >> (shift+8)) == prefix);
            if (ok) atomicAdd(&hist[(key>>shift)&255u], 1u);
        }
        __syncthreads();
        if (tid==0){
            unsigned cum = sAbove;
            unsigned above = sAbove;
            int bsel = 0;
            for (int bin=255; bin>=0; bin--){
                unsigned h = hist[bin];
                if (cum + h >= TGT){ bsel = bin; above = cum; break; }
                cum += h;
            }
            sSel   = (sSel<<8) | (unsigned)bsel;
            sAbove = above;
        }
        __syncthreads();
    }
    if (tid==0){
        unsigned tk = sSel << 6;
        float tau = __uint_as_float(tk);
        if (!(tau > 1e-30f)) tau = 1e-30f;
        if (tau > 0.999999f) tau = 0.999999f;
        g_tauV[b] = tau * (1.0f - 1e-3f);
        g_tauL[b] = logf(tau/(1.0f - tau)) - 1e-3f;
    }
}

// ---------------------------------------------------------------------------
// Kernel 1: the streaming filter. Reads every logit exactly once (float4),
// compares raw logit vs tauL (sigmoid is monotone). Last-channel elements
// get sigmoid*obj vs tauV. Survivors push their flat index.
// ---------------------------------------------------------------------------
__global__ __launch_bounds__(256) void k_filter(const float* __restrict__ logits,
                                                const float* __restrict__ obj)
{
    int b = blockIdx.y;
    const float tauL = g_tauL[b];
    const float tauV = g_tauV[b];
    const float4* L4 = (const float4*)(logits + (size_t)b*NPB);
    const float*  O  = obj + (size_t)b*QQ;

    unsigned base   = blockIdx.x*blockDim.x + threadIdx.x;
    const unsigned stride = gridDim.x*blockDim.x;

    unsigned ii[4]; bool act[4]; float4 val[4];
    #pragma unroll
    for (int j=0;j<4;j++){
        unsigned i = base + (unsigned)j*stride;
        act[j] = (i < (unsigned)NF4);
        ii[j]  = act[j] ? i : 0u;
    }
    #pragma unroll
    for (int j=0;j<4;j++) if (act[j]) val[j] = __ldg(&L4[ii[j]]);

    #pragma unroll
    for (int j=0;j<4;j++){
        if (!act[j]) continue;
        unsigned e = ii[j]*4u;
        unsigned q = e/(unsigned)CC;
        unsigned r = e - q*(unsigned)CC;
        float fs[4] = {val[j].x, val[j].y, val[j].z, val[j].w};
        #pragma unroll
        for (int t=0;t<4;t++){
            unsigned c = r + (unsigned)t;
            unsigned qq = q;
            if (c >= (unsigned)CC){ c -= (unsigned)CC; qq++; }
            bool push;
            if (c == (unsigned)(CC-1)){
                float s = fsig_fast(fs[t]) * O[qq];
                push = (s >= tauV);
            } else {
                push = (fs[t] >= tauL);
            }
            if (push){
                unsigned p = atomicAdd(&g_cnt[b], 1u);
                if (p < CAP) g_cand[b][p] = e + (unsigned)t;
            }
        }
    }
}

// ---------------------------------------------------------------------------
// Kernel 2: per-batch exact top-100 via 64-bit MSB radix-select + rank sort.
// Keys: (float_bits(prob) << 32) | ~idx  -> u64 descending == jax top_k order.
// Slow path (statistically unreachable) is a correct bounded full rescan.
// ---------------------------------------------------------------------------
__global__ __launch_bounds__(512) void k_select(const float* __restrict__ logits,
                                                const float* __restrict__ obj,
                                                const float* __restrict__ boxes,
                                                const int*   __restrict__ tsraw,
                                                float* __restrict__ dout)
{
    int b   = blockIdx.x;
    int tid = threadIdx.x;
    const float* L = logits + (size_t)b*NPB;
    const float* O = obj    + (size_t)b*QQ;

    __shared__ unsigned long long keys[SHCAP];      // 45056 B
    __shared__ unsigned long long outk[KTOP];       //   800 B
    __shared__ unsigned           hist[256];        //  1024 B
    __shared__ unsigned long long wmax[16];
    __shared__ unsigned long long sPrefix;
    __shared__ unsigned           sRemain, sNc;
    __shared__ unsigned long long sPrev;

    unsigned cnt = g_cnt[b];
    bool bad = (cnt < (unsigned)KTOP) || (cnt > (unsigned)SHCAP);
    int lane = tid & 31, wid = tid >> 5;

    if (!bad){
        int n = (int)cnt;
        // exact value recompute for all candidates
        for (int i=tid; i<n; i+=512){
            unsigned idx = g_cand[b][i];
            float lg = L[idx];
            float v  = fsig_acc(lg);
            unsigned q = idx/(unsigned)CC;
            unsigned c = idx - q*(unsigned)CC;
            if (c == (unsigned)(CC-1)) v *= O[q];
            keys[i] = ((unsigned long long)__float_as_uint(v) << 32)
                    | (unsigned)(~idx);
        }
        if (tid==0){ sPrefix = 0ull; sRemain = KTOP; sNc = 0u; }
        __syncthreads();

        // ---- 8-pass MSB radix select: exact KTOP-th largest key ----------
        for (int d=7; d>=0; d--){
            if (tid < 256) hist[tid] = 0u;
            __syncthreads();
            unsigned long long pref = sPrefix;
            unsigned rem = sRemain;
            int shift = d*8;
            for (int i=tid; i<n; i+=512){
                unsigned long long kk = keys[i];
                bool m = (d==7) || ((kk >> (shift+8)) == pref);
                if (m) atomicAdd(&hist[(unsigned)(kk>>shift)&255u], 1u);
            }
            __syncthreads();
            if (wid==0){
                // lane l covers bins [255-8l .. 248-8l] (descending)
                int base = 255 - lane*8;
                unsigned h[8]; unsigned sum=0;
                #pragma unroll
                for (int j=0;j<8;j++){ h[j]=hist[base-j]; sum+=h[j]; }
                unsigned inc = sum;
                #pragma unroll
                for (int off=1; off<32; off<<=1){
                    unsigned o = __shfl_up_sync(0xFFFFFFFFu, inc, off);
                    if (lane>=off) inc += o;
                }
                unsigned excl = inc - sum;
                if (excl < rem && rem <= inc){
                    unsigned r = rem - excl;
                    unsigned c = 0; int dig = base;
                    for (int j=0;j<8;j++){
                        if (c + h[j] >= r){ dig = base - j; break; }
                        c += h[j];
                    }
                    sPrefix = (pref<<8) | (unsigned long long)(unsigned)dig;
                    sRemain = r - c;
                }
            }
            __syncthreads();
        }
        unsigned long long pivot = sPrefix;

        // ---- collect the exactly-KTOP keys >= pivot -----------------------
        for (int i=tid; i<n; i+=512){
            unsigned long long kk = keys[i];
            if (kk >= pivot){
                unsigned p = atomicAdd(&sNc, 1u);
                if (p < (unsigned)KTOP) outk[p] = kk;
            }
        }
        __syncthreads();

        // ---- rank sort of 100 keys (unique) -------------------------------
        unsigned long long myk = 0ull; int rank = 0;
        if (tid < KTOP){
            myk = outk[tid];
            for (int j=0;j<KTOP;j++) rank += (outk[j] > myk) ? 1 : 0;
        }
        __syncthreads();
        if (tid < KTOP) outk[rank] = myk;
        __syncthreads();
    } else {
        // Fully correct fallback: 100 bounded full-batch argmax passes.
        if (tid==0) sPrev = 0xFFFFFFFFFFFFFFFFull;
        __syncthreads();
        for (int k=0;k<KTOP;k++){
            unsigned long long prev = sPrev;
            unsigned long long bm = 0ull;
            for (unsigned i=tid; i<(unsigned)NPB; i+=512u){
                float lg = L[i];
                float v  = fsig_acc(lg);
                unsigned q = i/(unsigned)CC;
                unsigned c = i - q*(unsigned)CC;
                if (c == (unsigned)(CC-1)) v *= O[q];
                unsigned long long kk =
                    ((unsigned long long)__float_as_uint(v) << 32) | (unsigned)(~i);
                if (kk < prev && kk > bm) bm = kk;
            }
            #pragma unroll
            for (int off=16; off; off>>=1){
                unsigned long long om = __shfl_down_sync(0xFFFFFFFFu, bm, off);
                if (om > bm) bm = om;
            }
            if (lane==0) wmax[wid]=bm;
            __syncthreads();
            if (tid==0){
                unsigned long long best=0ull;
                for (int w=0;w<16;w++) if (wmax[w]>best) best=wmax[w];
                outk[k]=best; sPrev=best;
            }
            __syncthreads();
        }
    }

    // ---- target_sizes: detect int64 vs int32 materialization -------------
    bool is64 = true;
    #pragma unroll
    for (int i2=1; i2<32; i2+=2) if (tsraw[i2] != 0) { is64 = false; }
    long long t0, t1;
    if (is64){
        const long long* p = (const long long*)tsraw;
        t0 = p[2*b]; t1 = p[2*b+1];
    } else {
        t0 = (long long)tsraw[2*b]; t1 = (long long)tsraw[2*b+1];
    }
    float scale = (float)(t0 > t1 ? t0 : t1);
    float limW  = (float)t1;
    float limH  = (float)t0;
    const float4* BX = (const float4*)boxes + (size_t)b*QQ;

    for (int k=tid; k<KTOP; k+=512){
        unsigned long long kk = outk[k];
        float    score = __uint_as_float((unsigned)(kk>>32));
        unsigned idx   = ~((unsigned)(kk & 0xFFFFFFFFull));
        unsigned q   = idx/(unsigned)CC;
        unsigned lab = idx - q*(unsigned)CC;

        dout[b*KTOP + k]            = score;
        dout[BB*KTOP + b*KTOP + k]  = (float)lab;

        float4 bx = BX[q];
        float x0 = (bx.x - 0.5f*bx.z)*scale;
        float y0 = (bx.y - 0.5f*bx.w)*scale;
        float x1 = (bx.x + 0.5f*bx.z)*scale;
        float y1 = (bx.y + 0.5f*bx.w)*scale;
        x0 = fminf(fmaxf(x0,0.0f), limW);
        y0 = fminf(fmaxf(y0,0.0f), limH);
        x1 = fminf(fmaxf(x1,0.0f), limW);
        y1 = fminf(fmaxf(y1,0.0f), limH);
        float* ob = dout + 2*BB*KTOP + ((size_t)(b*KTOP + k))*4;
        ob[0]=x0; ob[1]=y0; ob[2]=x1; ob[3]=y1;
    }
}

// ---------------------------------------------------------------------------
extern "C" void kernel_launch(void* const* d_in, const int* in_sizes, int n_in,
                              void* d_out, int out_size)
{
    const float* logits = (const float*)d_in[0];
    const float* obj    = (const float*)d_in[1];
    const float* boxes  = (const float*)d_in[2];
    const int*   tsraw  = (const int*)  d_in[3];
    float* dout = (float*)d_out;

    dim3 gg(NSAMP/256, BB);                  // (64, 16)
    k_gather<<<gg, 256>>>(logits, obj);
    k_refine<<<BB, 256>>>();

    dim3 gf((NF4 + 256*4 - 1)/(256*4), BB);  // (678, 16)
    k_filter<<<gf, 256>>>(logits, obj);

    k_select<<<BB, 512>>>(logits, obj, boxes, tsraw, dout);
}

// round 7
// speedup vs baseline: 2.1989x; 2.1989x over previous
#include <cuda_runtime.h>
#include <math.h>

#define BB 16
#define QQ 2304
#define CC 1204
#define NPB (QQ*CC)          /* 2774016 elements per batch */
#define NTOT (NPB*BB)        /* 44384256 total elements */
#define NF4ALL (NTOT/4)      /* 11096064 float4 total */
#define KTOP 100
#define CAP 4096             /* per-batch candidate store (u64 keys) */
#define TAUL 3.49f           /* fixed logit threshold; E[cnt]~668/batch.
                                Correctness does NOT depend on it: k_select
                                falls back to a full exact rescan whenever
                                cnt < KTOP or cnt > CAP. */

__device__ unsigned           g_cnt[BB];        /* zero-init; reset by k_select */
__device__ unsigned long long g_key[BB][CAP];

__device__ __forceinline__ float fsig_acc(float x){ return 1.0f/(1.0f+expf(-x)); }

// ---------------------------------------------------------------------------
// Kernel 1: streaming filter over ALL batches flat. Hot loop: 4x LDG.128 +
// fmax tree + 1 compare per 16 elements. Rare hits (~670/batch) compute the
// EXACT value (accurate expf, obj multiply for last channel) and push a
// 64-bit key: (float_bits(value) << 32) | ~local_idx  -> descending u64
// order == jax.lax.top_k order (value desc, index asc).
// ---------------------------------------------------------------------------
__global__ __launch_bounds__(256) void k_filter(const float* __restrict__ logits,
                                                const float* __restrict__ obj)
{
    const float4* L4 = (const float4*)logits;
    unsigned base   = blockIdx.x*blockDim.x + threadIdx.x;
    const unsigned stride = gridDim.x*blockDim.x;

    unsigned ii[4]; bool act[4]; float4 v[4];
    #pragma unroll
    for (int j=0;j<4;j++){
        unsigned i = base + (unsigned)j*stride;
        act[j] = (i < (unsigned)NF4ALL);
        ii[j]  = act[j] ? i : 0u;
    }
    #pragma unroll
    for (int j=0;j<4;j++) if (act[j]) v[j] = __ldg(&L4[ii[j]]);

    #pragma unroll
    for (int j=0;j<4;j++){
        if (!act[j]) continue;
        float m = fmaxf(fmaxf(v[j].x, v[j].y), fmaxf(v[j].z, v[j].w));
        if (m >= TAUL){
            float fs[4] = {v[j].x, v[j].y, v[j].z, v[j].w};
            #pragma unroll
            for (int t=0;t<4;t++){
                if (fs[t] >= TAUL){
                    unsigned e     = ii[j]*4u + (unsigned)t;
                    unsigned b     = e / (unsigned)NPB;
                    unsigned local = e - b*(unsigned)NPB;
                    unsigned q     = local/(unsigned)CC;
                    unsigned c     = local - q*(unsigned)CC;
                    float val = fsig_acc(fs[t]);
                    if (c == (unsigned)(CC-1)) val *= __ldg(&obj[b*(unsigned)QQ + q]);
                    unsigned long long key =
                        ((unsigned long long)__float_as_uint(val) << 32)
                      | (unsigned)(~local);
                    unsigned p = atomicAdd(&g_cnt[b], 1u);
                    if (p < (unsigned)CAP) g_key[b][p] = key;
                }
            }
        }
    }
}

// ---------------------------------------------------------------------------
// Kernel 2: per-batch exact top-100 via 64-bit MSB radix-select over the
// compact (L2-hot) key buffer, then rank sort + box epilogue.
// Slow path (statistically unreachable, but required for unconditional
// correctness) is a bounded full-batch rescan. Resets g_cnt for the next
// graph replay.
// ---------------------------------------------------------------------------
__global__ __launch_bounds__(512) void k_select(const float* __restrict__ logits,
                                                const float* __restrict__ obj,
                                                const float* __restrict__ boxes,
                                                const int*   __restrict__ tsraw,
                                                float* __restrict__ dout)
{
    int b   = blockIdx.x;
    int tid = threadIdx.x;
    const float* L = logits + (size_t)b*NPB;
    const float* O = obj    + (size_t)b*QQ;

    __shared__ unsigned long long keys[CAP];        // 32 KB
    __shared__ unsigned long long outk[KTOP];
    __shared__ unsigned           hist[256];
    __shared__ unsigned long long wmax[16];
    __shared__ unsigned long long sPrefix;
    __shared__ unsigned           sRemain, sNc, sCnt;
    __shared__ unsigned long long sPrev;

    if (tid==0){ sCnt = g_cnt[b]; g_cnt[b] = 0u; }   // read + reset (replay invariant)
    __syncthreads();
    unsigned cnt = sCnt;
    bool bad = (cnt < (unsigned)KTOP) || (cnt > (unsigned)CAP);
    int lane = tid & 31, wid = tid >> 5;

    if (!bad){
        int n = (int)cnt;
        for (int i=tid; i<n; i+=512) keys[i] = g_key[b][i];
        if (tid==0){ sPrefix = 0ull; sRemain = KTOP; sNc = 0u; }
        __syncthreads();

        // ---- 8-pass MSB radix select: exact KTOP-th largest key ----------
        for (int d=7; d>=0; d--){
            if (tid < 256) hist[tid] = 0u;
            __syncthreads();
            unsigned long long pref = sPrefix;
            unsigned rem = sRemain;
            int shift = d*8;
            for (int i=tid; i<n; i+=512){
                unsigned long long kk = keys[i];
                bool m = (d==7) || ((kk >> (shift+8)) == pref);
                if (m) atomicAdd(&hist[(unsigned)(kk>>shift)&255u], 1u);
            }
            __syncthreads();
            if (wid==0){
                int base = 255 - lane*8;            // lane covers 8 bins, descending
                unsigned h[8]; unsigned sum=0;
                #pragma unroll
                for (int j=0;j<8;j++){ h[j]=hist[base-j]; sum+=h[j]; }
                unsigned inc = sum;
                #pragma unroll
                for (int off=1; off<32; off<<=1){
                    unsigned o = __shfl_up_sync(0xFFFFFFFFu, inc, off);
                    if (lane>=off) inc += o;
                }
                unsigned excl = inc - sum;
                if (excl < rem && rem <= inc){
                    unsigned r = rem - excl;
                    unsigned c = 0; int dig = base;
                    for (int j=0;j<8;j++){
                        if (c + h[j] >= r){ dig = base - j; break; }
                        c += h[j];
                    }
                    sPrefix = (pref<<8) | (unsigned long long)(unsigned)dig;
                    sRemain = r - c;
                }
            }
            __syncthreads();
        }
        unsigned long long pivot = sPrefix;

        // ---- collect the exactly-KTOP keys >= pivot (keys are unique) ----
        for (int i=tid; i<n; i+=512){
            unsigned long long kk = keys[i];
            if (kk >= pivot){
                unsigned p = atomicAdd(&sNc, 1u);
                if (p < (unsigned)KTOP) outk[p] = kk;
            }
        }
        __syncthreads();

        // ---- rank sort of 100 unique keys ---------------------------------
        unsigned long long myk = 0ull; int rank = 0;
        if (tid < KTOP){
            myk = outk[tid];
            for (int j=0;j<KTOP;j++) rank += (outk[j] > myk) ? 1 : 0;
        }
        __syncthreads();
        if (tid < KTOP) outk[rank] = myk;
        __syncthreads();
    } else {
        // Fully correct fallback: 100 bounded full-batch argmax passes.
        if (tid==0) sPrev = 0xFFFFFFFFFFFFFFFFull;
        __syncthreads();
        for (int k=0;k<KTOP;k++){
            unsigned long long prev = sPrev;
            unsigned long long bm = 0ull;
            for (unsigned i=tid; i<(unsigned)NPB; i+=512u){
                float lg = L[i];
                float v  = fsig_acc(lg);
                unsigned q = i/(unsigned)CC;
                unsigned c = i - q*(unsigned)CC;
                if (c == (unsigned)(CC-1)) v *= O[q];
                unsigned long long kk =
                    ((unsigned long long)__float_as_uint(v) << 32) | (unsigned)(~i);
                if (kk < prev && kk > bm) bm = kk;
            }
            #pragma unroll
            for (int off=16; off; off>>=1){
                unsigned long long om = __shfl_down_sync(0xFFFFFFFFu, bm, off);
                if (om > bm) bm = om;
            }
            if (lane==0) wmax[wid]=bm;
            __syncthreads();
            if (tid==0){
                unsigned long long best=0ull;
                for (int w=0;w<16;w++) if (wmax[w]>best) best=wmax[w];
                outk[k]=best; sPrev=best;
            }
            __syncthreads();
        }
    }

    // ---- target_sizes: detect int64 vs int32 materialization -------------
    bool is64 = true;
    #pragma unroll
    for (int i2=1; i2<32; i2+=2) if (tsraw[i2] != 0) { is64 = false; }
    long long t0, t1;
    if (is64){
        const long long* p = (const long long*)tsraw;
        t0 = p[2*b]; t1 = p[2*b+1];
    } else {
        t0 = (long long)tsraw[2*b]; t1 = (long long)tsraw[2*b+1];
    }
    float scale = (float)(t0 > t1 ? t0 : t1);
    float limW  = (float)t1;
    float limH  = (float)t0;
    const float4* BX = (const float4*)boxes + (size_t)b*QQ;

    for (int k=tid; k<KTOP; k+=512){
        unsigned long long kk = outk[k];
        float    score = __uint_as_float((unsigned)(kk>>32));
        unsigned idx   = ~((unsigned)(kk & 0xFFFFFFFFull));
        unsigned q   = idx/(unsigned)CC;
        unsigned lab = idx - q*(unsigned)CC;

        dout[b*KTOP + k]            = score;
        dout[BB*KTOP + b*KTOP + k]  = (float)lab;

        float4 bx = BX[q];
        float x0 = (bx.x - 0.5f*bx.z)*scale;
        float y0 = (bx.y - 0.5f*bx.w)*scale;
        float x1 = (bx.x + 0.5f*bx.z)*scale;
        float y1 = (bx.y + 0.5f*bx.w)*scale;
        x0 = fminf(fmaxf(x0,0.0f), limW);
        y0 = fminf(fmaxf(y0,0.0f), limH);
        x1 = fminf(fmaxf(x1,0.0f), limW);
        y1 = fminf(fmaxf(y1,0.0f), limH);
        float* ob = dout + 2*BB*KTOP + ((size_t)(b*KTOP + k))*4;
        ob[0]=x0; ob[1]=y0; ob[2]=x1; ob[3]=y1;
    }
}

// ---------------------------------------------------------------------------
extern "C" void kernel_launch(void* const* d_in, const int* in_sizes, int n_in,
                              void* d_out, int out_size)
{
    const float* logits = (const float*)d_in[0];
    const float* obj    = (const float*)d_in[1];
    const float* boxes  = (const float*)d_in[2];
    const int*   tsraw  = (const int*)  d_in[3];
    float* dout = (float*)d_out;

    unsigned grid = (NF4ALL + 256*4 - 1)/(256*4);   // 10836 blocks, flat stream
    k_filter<<<grid, 256>>>(logits, obj);

    k_select<<<BB, 512>>>(logits, obj, boxes, tsraw, dout);
}